// round 12
// baseline (speedup 1.0000x reference)
#include <cuda_runtime.h>
#include <math.h>

// Problem constants
#define B_   4
#define H_   16
#define NF_  32
#define P_   16
#define M_   257          // P*P + 1
#define S_   (NF_ * M_)   // 8224
#define D_   64
#define NTOK (B_ * H_ * S_)   // 526336 tokens per tensor

// Separable cos/sin table: pairs 0-4 depend only on frame (32 values),
// pairs 5-9 only on r (17), pairs 10-14 only on c (17).
// Layout: [0,160)   = frame*5 + j      (axis 0)
//         [160,245) = 160 + r*5 + j    (axis 1)
//         [245,330) = 245 + c*5 + j    (axis 2)
//         [330]     = identity (cos=1, sin=0) for the non-rotated pair slot
#define TBL_SMALL 331
__device__ float2 g_cs[TBL_SMALL];

__device__ __forceinline__ int cs_idx(int p, int frame, int r, int c) {
    if (p < 5)  return frame * 5 + p;
    if (p < 10) return 160 + r * 5 + (p - 5);
    if (p < 15) return 245 + c * 5 + (p - 10);
    return 330;                           // identity entry
}

// Fast sincos for |x| <= ~403 rad: range-reduce in double (1 DMUL + rint +
// 1 DFMA, error ~1e-15), then MUFU __sinf/__cosf on [-pi, pi]
// (abs err ~5e-7; gate is 1e-3). Avoids libm's Payne-Hanek slow path.
__device__ __forceinline__ float2 fast_cs(float f) {
    const double TWO_PI  = 6.283185307179586476925286766559;
    const double INV_2PI = 0.15915494309189533576888376337251;
    double d  = (double)f;
    double kq = rint(d * INV_2PI);
    float  r  = (float)(d - kq * TWO_PI);   // reduced arg in [-pi, pi]
    return make_float2(__cosf(r), __sinf(r));
}

// ---------------------------------------------------------------------------
// Precompute: 331 unique cos/sin entries, one block, ~1us. Fires the PDL
// trigger so the dependent main kernel can start overlapped.
// ---------------------------------------------------------------------------
__global__ void precompute_cs_kernel(const float* __restrict__ freqs) {
    int i = threadIdx.x;
    if (i < TBL_SMALL) {
        if (i == 330) {
            g_cs[i] = make_float2(1.0f, 0.0f);
        } else {
            float f;
            if (i < 160) {
                int frame = i / 5, j = i - frame * 5;
                f = freqs[((frame * 17 + 0) * 17 + 0) * 30 + 2 * j];
            } else if (i < 245) {
                int kk = i - 160;
                int r = kk / 5, j = kk - r * 5;
                f = freqs[((0 * 17 + r) * 17 + 0) * 30 + 10 + 2 * j];
            } else {
                int kk = i - 245;
                int c = kk / 5, j = kk - c * 5;
                f = freqs[((0 * 17 + 0) * 17 + c) * 30 + 20 + 2 * j];
            }
            g_cs[i] = fast_cs(f);
        }
    }
    cudaTriggerProgrammaticLaunchCompletion();
}

// ---------------------------------------------------------------------------
// Main RoPE kernel — R2 shape (best measured: 75.17us, DRAM 81.1%).
// 8 threads per token; thread t handles float4 chunks t (rotated) and t+8
// (copy) of ONE tensor; q = gids [0, NTOK*8), k = [NTOK*8, 2*NTOK*8).
// Launched with PDL: stream loads issue immediately; gridsync only guards
// the g_cs table reads.
// ---------------------------------------------------------------------------
__global__ __launch_bounds__(256) void frame_rope_kernel(
        const float4* __restrict__ q,
        const float4* __restrict__ k,
        float4*       __restrict__ out) {
    int gid  = blockIdx.x * blockDim.x + threadIdx.x;  // < 2*NTOK*8
    int t    = gid & 7;         // chunk id within token (0..7)
    int tokg = gid >> 3;        // global token id across both tensors

    const float4* src;
    int tok;
    if (tokg < NTOK) { src = q; tok = tokg; }
    else             { src = k; tok = tokg - NTOK; }

    const float4* base = src + tok * 16;
    // Independent of the precompute output — issue before gridsync.
    float4 v0 = base[t];        // rotated half (dims 0..31)
    float4 v1 = base[t + 8];    // pure copy half

    // Position -> (frame, r, c); audio token (m==256) -> (16,16).
    int s     = tok % S_;
    int frame = s / M_;
    int m     = s - frame * M_;
    int r, c;
    if (m == 256) { r = 16; c = 16; }
    else          { r = m >> 4; c = m & 15; }

    // Wait for the precompute grid's writes to be visible, then read table.
    cudaGridDependencySynchronize();

    int p0 = 2 * t;             // pair covering (v0.x, v0.y); always < 15
    float2 cs0 = g_cs[cs_idx(p0,     frame, r, c)];
    float2 cs1 = g_cs[cs_idx(p0 + 1, frame, r, c)];  // p0+1==15 -> identity

    float4 o0;
    o0.x = v0.x * cs0.x - v0.y * cs0.y;
    o0.y = v0.y * cs0.x + v0.x * cs0.y;
    o0.z = v0.z * cs1.x - v0.w * cs1.y;
    o0.w = v0.w * cs1.x + v0.z * cs1.y;

    float4* obase = out + tokg * 16;
    obase[t]     = o0;
    obase[t + 8] = v1;
}

extern "C" void kernel_launch(void* const* d_in, const int* in_sizes, int n_in,
                              void* d_out, int out_size) {
    const float* q     = (const float*)d_in[0];
    const float* k     = (const float*)d_in[1];
    const float* freqs = (const float*)d_in[2];

    precompute_cs_kernel<<<1, 352>>>(freqs);

    // Main kernel with Programmatic Dependent Launch: overlaps its launch/
    // ramp-up with the (tiny) precompute kernel instead of serializing.
    cudaLaunchConfig_t cfg = {};
    cfg.gridDim  = dim3((2 * NTOK * 8) / 256);   // 32,896 blocks
    cfg.blockDim = dim3(256);
    cfg.dynamicSmemBytes = 0;
    cfg.stream = 0;
    cudaLaunchAttribute attr[1];
    attr[0].id = cudaLaunchAttributeProgrammaticStreamSerialization;
    attr[0].val.programmaticStreamSerializationAllowed = 1;
    cfg.attrs = attr;
    cfg.numAttrs = 1;
    cudaLaunchKernelEx(&cfg, frame_rope_kernel,
                       (const float4*)q, (const float4*)k, (float4*)d_out);
}

// round 13
// speedup vs baseline: 1.0328x; 1.0328x over previous
#include <cuda_runtime.h>
#include <math.h>

// Problem constants
#define B_   4
#define H_   16
#define NF_  32
#define P_   16
#define M_   257          // P*P + 1
#define S_   (NF_ * M_)   // 8224
#define D_   64
#define NTOK (B_ * H_ * S_)   // 526336 tokens per tensor

// ---------------------------------------------------------------------------
// Pure-fp32 sincos for |x| <= ~403 rad.
// Cody-Waite: 2*pi = C0 + C1 with C0 = 6.28125 (9 mantissa bits, so k*C0 is
// EXACT for k <= 64) and C1 = 2*pi - 6.28125 = 1.9353071795864769e-3
// (correctly rounded; omitted residual contributes < 1e-8 rad).
// Then MUFU __sinf/__cosf on [-pi, pi]: abs err ~4e-7. Gate is 1e-3.
// ---------------------------------------------------------------------------
__device__ __forceinline__ float2 fast_cs(float f) {
    const float INV_2PI = 0.15915494309189533f;
    const float C0 = 6.28125f;                    // exact; k*C0 exact (k<=64)
    const float C1 = 1.9353071795864769e-3f;      // 2*pi - C0, correctly rounded
    float kf = rintf(f * INV_2PI);
    float r  = fmaf(-kf, C0, f);
    r        = fmaf(-kf, C1, r);
    return make_float2(__cosf(r), __sinf(r));
}

// Freq element index for pair p at grid cell (frame, r, c).
// freqs shape (32,17,17,30): dims [0,10) depend on frame, [10,20) on r,
// [20,30) on c; adjacent dims repeat, so pair p uses element 2*(p%5) of its
// axis block. Working set: ~330 distinct addresses -> L1-resident.
__device__ __forceinline__ int freq_idx(int p, int frame, int r, int c) {
    if (p < 5)  return frame * (17 * 17 * 30) + 2 * p;
    if (p < 10) return r * (17 * 30) + 10 + 2 * (p - 5);
    return c * 30 + 20 + 2 * (p - 10);
}

// ---------------------------------------------------------------------------
// Single fused kernel, no smem/barrier/table. 8 threads per seq-position;
// thread t handles float4 chunks t (rotated) and t+8 (copy) of BOTH the q
// and k tokens at the same (b,h,s). 4 independent streaming loads; the two
// cos/sin pairs are computed inline (fp32 Cody-Waite + MUFU) and amortized
// across q and k.
// ---------------------------------------------------------------------------
__global__ __launch_bounds__(256) void frame_rope_kernel(
        const float*  __restrict__ freqs,
        const float4* __restrict__ q,
        const float4* __restrict__ k,
        float4*       __restrict__ out) {
    int gid = blockIdx.x * blockDim.x + threadIdx.x;   // < NTOK*8
    int t   = gid & 7;          // chunk id within token (0..7)
    int tok = gid >> 3;         // token id (same for q and k)

    const float4* qb = q + tok * 16;
    const float4* kb = k + tok * 16;
    // Front-batch all four independent streaming loads (single-use data).
    float4 q0 = __ldcs(qb + t);
    float4 q1 = __ldcs(qb + t + 8);
    float4 k0 = __ldcs(kb + t);
    float4 k1 = __ldcs(kb + t + 8);

    // Position -> (frame, r, c); audio token (m==256) -> cell (16,16).
    int s     = tok % S_;
    int frame = s / M_;
    int m     = s - frame * M_;
    int r, c;
    if (m == 256) { r = 16; c = 16; }
    else          { r = m >> 4; c = m & 15; }

    // Inline cos/sin for pairs p0 = 2t and p0+1 (p0+1==15 -> identity).
    int p0 = 2 * t;
    float f0 = __ldg(freqs + freq_idx(p0, frame, r, c));
    float2 cs0 = fast_cs(f0);
    float2 cs1 = make_float2(1.0f, 0.0f);
    if (t < 7) {
        float f1 = __ldg(freqs + freq_idx(p0 + 1, frame, r, c));
        cs1 = fast_cs(f1);
    }

    float4 oq, ok;
    oq.x = q0.x * cs0.x - q0.y * cs0.y;
    oq.y = q0.y * cs0.x + q0.x * cs0.y;
    oq.z = q0.z * cs1.x - q0.w * cs1.y;
    oq.w = q0.w * cs1.x + q0.z * cs1.y;
    ok.x = k0.x * cs0.x - k0.y * cs0.y;
    ok.y = k0.y * cs0.x + k0.x * cs0.y;
    ok.z = k0.z * cs1.x - k0.w * cs1.y;
    ok.w = k0.w * cs1.x + k0.z * cs1.y;

    float4* oqb = out + tok * 16;
    float4* okb = out + (NTOK + tok) * 16;
    __stcs(oqb + t,     oq);
    __stcs(oqb + t + 8, q1);
    __stcs(okb + t,     ok);
    __stcs(okb + t + 8, k1);
}

extern "C" void kernel_launch(void* const* d_in, const int* in_sizes, int n_in,
                              void* d_out, int out_size) {
    const float* q     = (const float*)d_in[0];
    const float* k     = (const float*)d_in[1];
    const float* freqs = (const float*)d_in[2];

    const int total_threads = NTOK * 8;   // 4,210,688 -> 16,448 blocks
    frame_rope_kernel<<<total_threads / 256, 256>>>(
        freqs, (const float4*)q, (const float4*)k, (float4*)d_out);
}